// round 7
// baseline (speedup 1.0000x reference)
#include <cuda_runtime.h>

// Problem constants (fixed shapes from reference):
//   x:          [16,64,64,256] fp32  -> N_ROWS=65536 rows of D_DIM=256
//   dictionary: [256,1024]     fp32  -> D_DIM x K_CODES
// Output: q_st (16777216 fp32) followed by loss (1 fp32).
//
// CORRECTNESS-CRITICAL: the reference (XLA CPU fp32) computes
//   t2(k) = fl( fl(nf + c_k) - fl(2 * sim_k) ),  argmin_k first-index,
// where nf/c_k are sequential fp32 square-sums over d=0..255 and sim is an
// fp32 FMA chain over d=0..255. Distances sit near 256 (quantized at
// ulp(256)=3.05e-5); matching the argmin requires replicating this
// arithmetic exactly. The packed f32x2 FMAs below are PER-LANE IEEE fp32
// FMAs in the same d order -> each scalar chain is bitwise identical to the
// unpacked version. Do NOT change accumulation order or fuse/unfuse ops.
#define D_DIM   256
#define K_CODES 1024
#define N_ROWS  65536

#define MTILE   128
#define NTILE   128
#define KCHUNK  32
#define ASTRIDE 260     // padded row stride for x tile (260 % 32 == 4 -> conflict-free LDS)
#define THREADS 256
#define NCHUNK  ((K_CODES / NTILE) * (D_DIM / KCHUNK))   // 64 dict chunks

// Scratch (no cudaMalloc allowed): transposed dictionary + code norms + loss accum
__device__ float  g_dictT[K_CODES * D_DIM];
__device__ float  g_c[K_CODES];
__device__ double g_loss;

// ---- packed f32x2 helpers (Blackwell FFMA2 path) --------------------------
__device__ __forceinline__ unsigned long long pack2(float lo, float hi) {
    unsigned long long r;
    asm("mov.b64 %0, {%1, %2};" : "=l"(r) : "f"(lo), "f"(hi));
    return r;
}
__device__ __forceinline__ void fma2(unsigned long long& acc,
                                     unsigned long long a,
                                     unsigned long long b) {
    asm("fma.rn.f32x2 %0, %1, %2, %0;" : "+l"(acc) : "l"(a), "l"(b));
}
__device__ __forceinline__ float2 unpack2(unsigned long long v) {
    float2 f;
    asm("mov.b64 {%0, %1}, %2;" : "=f"(f.x), "=f"(f.y) : "l"(v));
    return f;
}

// ---------------------------------------------------------------------------
// Kernel 1a: smem-tiled transpose dict[d][k] -> g_dictT[k][d], coalesced on
// both sides (fixes the 43us uncoalesced-store prep of the previous round).
// ---------------------------------------------------------------------------
__global__ void vq_transpose(const float* __restrict__ dict) {
    __shared__ float tile[32][33];
    const int kb = blockIdx.x * 32;       // code base
    const int db = blockIdx.y * 32;       // dim base
    const int tx = threadIdx.x & 31;
    const int ty = threadIdx.x >> 5;      // 8 rows of loaders
    #pragma unroll
    for (int r = ty; r < 32; r += 8)
        tile[r][tx] = dict[(size_t)(db + r) * K_CODES + kb + tx];
    __syncthreads();
    #pragma unroll
    for (int r = ty; r < 32; r += 8)
        g_dictT[(size_t)(kb + r) * D_DIM + db + tx] = tile[tx][r];
}

// ---------------------------------------------------------------------------
// Kernel 1b: c_k = sum_d fl(d*d), SEQUENTIAL fp32 adds in d order (order is
// load-bearing for the argmin grid). Coalesced loads, no bulk stores.
// ---------------------------------------------------------------------------
__global__ void vq_norms(const float* __restrict__ dict) {
    int k = blockIdx.x * blockDim.x + threadIdx.x;
    if (k == 0) g_loss = 0.0;
    if (k < K_CODES) {
        float c = 0.f;
        for (int d = 0; d < D_DIM; ++d) {
            float v = dict[(size_t)d * K_CODES + k];
            c = __fadd_rn(c, __fmul_rn(v, v));         // no FMA contraction
        }
        g_c[k] = c;
    }
}

// ---------------------------------------------------------------------------
// Kernel 2: per 128-row tile: sim = f.d_k as sequential fp32 FMA chains over
// d=0..255 (packed 2 codes per FFMA2; per-lane order identical), then the
// reference's rounding t1 = fl(nf + c_k), t2 = fl(t1 - fl(2*sim)), argmin
// first-index. Gather q = 0.5*dictT[k*] (exact), write output, accum loss.
// Thread map: j = t&15 owns 8 codes (4 packed pairs), i = t>>4 owns rows
// {i, i+16, ..., i+112}. sB is double-buffered with register-staged LDG
// prefetch: one barrier per chunk.
// ---------------------------------------------------------------------------
__global__ __launch_bounds__(THREADS, 1)
void vq_main(const float* __restrict__ x,
             const float* __restrict__ dict,
             float* __restrict__ out) {
    extern __shared__ float smem[];
    float* sA   = smem;                              // MTILE*ASTRIDE (x tile)
    float* sB   = sA + MTILE * ASTRIDE;              // 2 * KCHUNK*NTILE (dict, ping-pong)
    float* sBv  = sB + 2 * KCHUNK * NTILE;           // MTILE*16 best values
    int*   sBi  = (int*)(sBv + MTILE * 16);          // MTILE*16 best indices
    int*   sIdx = sBi + MTILE * 16;                  // MTILE final indices
    float* sNf  = (float*)(sIdx + MTILE);            // MTILE row norms ||f||^2

    const int t = threadIdx.x;
    const int j = t & 15;
    const int i = t >> 4;
    const size_t row0 = (size_t)blockIdx.x * MTILE;

    // Load x tile (float4, coalesced) into padded SMEM
    {
        const float4* xv = (const float4*)(x + row0 * D_DIM);
        for (int e = t; e < MTILE * (D_DIM / 4); e += THREADS) {
            int r  = e >> 6;          // D_DIM/4 == 64
            int c4 = e & 63;
            float4 v = xv[r * 64 + c4];
            float* dst = sA + r * ASTRIDE + c4 * 4;
            dst[0] = v.x; dst[1] = v.y; dst[2] = v.z; dst[3] = v.w;
        }
    }

    // Prefetch dict chunk 0 into registers while sA settles
    float4 pf[4];
    {
        #pragma unroll
        for (int q = 0; q < 4; ++q) {
            int e  = t + THREADS * q;             // float4 slot in chunk
            int r  = e >> 5;                      // NTILE/4 == 32 slots/row
            int c4 = e & 31;
            pf[q] = *(const float4*)(dict + (size_t)r * K_CODES + c4 * 4);
        }
    }
    __syncthreads();

    // Per-row nf = sum_d fl(x*x), sequential fp32 adds in d order.
    if (t < MTILE) {
        float s = 0.f;
        const float* rowp = sA + t * ASTRIDE;
        for (int d = 0; d < D_DIM; ++d)
            s = __fadd_rn(s, __fmul_rn(rowp[d], rowp[d]));
        sNf[t] = s;
    }

    // Stage chunk 0 into buffer 0
    {
        #pragma unroll
        for (int q = 0; q < 4; ++q) {
            int e  = t + THREADS * q;
            int r  = e >> 5;
            int c4 = e & 31;
            *(float4*)(sB + r * NTILE + c4 * 4) = pf[q];
        }
    }
    __syncthreads();

    float nf_m[8];
    #pragma unroll
    for (int m = 0; m < 8; ++m) nf_m[m] = sNf[i + 16 * m];

    float bv[8];
    int   bi[8];
    #pragma unroll
    for (int m = 0; m < 8; ++m) { bv[m] = __int_as_float(0x7f800000); bi[m] = 0; }

    unsigned long long acc2[8][4];   // [row][code-pair]; lo=even code, hi=odd
    #pragma unroll
    for (int m = 0; m < 8; ++m)
        #pragma unroll
        for (int p = 0; p < 4; ++p) acc2[m][p] = 0ull;

    for (int c = 0; c < NCHUNK; ++c) {
        const int tt = c >> 3;            // code-tile index
        const int kt = c & 7;             // d-chunk within tile
        const float* sBuf = sB + (c & 1) * (KCHUNK * NTILE);

        // Prefetch next chunk (LDG overlapped with compute below)
        if (c + 1 < NCHUNK) {
            const int nt = (c + 1) >> 3, nk = (c + 1) & 7;
            const int base_d = nk * KCHUNK, base_c = nt * NTILE;
            #pragma unroll
            for (int q = 0; q < 4; ++q) {
                int e  = t + THREADS * q;
                int r  = e >> 5;
                int c4 = e & 31;
                pf[q] = *(const float4*)(dict + (size_t)(base_d + r) * K_CODES
                                         + base_c + c4 * 4);
            }
        }

        // Packed FMA chains, ascending d = kt*32+kk: ORDER IS LOAD-BEARING.
        const int colbase = kt * KCHUNK;
        #pragma unroll 8
        for (int kk = 0; kk < KCHUNK; ++kk) {
            unsigned long long a2[8];
            #pragma unroll
            for (int m = 0; m < 8; ++m) {
                float a = sA[(i + 16 * m) * ASTRIDE + colbase + kk];
                a2[m] = pack2(a, a);
            }
            // b pairs: adjacent codes are adjacent floats -> direct 16B loads
            const unsigned long long* bp =
                (const unsigned long long*)(sBuf + kk * NTILE + j * 8);
            ulonglong2 u0 = *(const ulonglong2*)(bp);
            ulonglong2 u1 = *(const ulonglong2*)(bp + 2);
            unsigned long long b2[4] = {u0.x, u0.y, u1.x, u1.y};
            #pragma unroll
            for (int m = 0; m < 8; ++m)
                #pragma unroll
                for (int p = 0; p < 4; ++p)
                    fma2(acc2[m][p], a2[m], b2[p]);
        }

        // Publish next chunk into the other buffer
        if (c + 1 < NCHUNK) {
            float* dst = sB + ((c + 1) & 1) * (KCHUNK * NTILE);
            #pragma unroll
            for (int q = 0; q < 4; ++q) {
                int e  = t + THREADS * q;
                int r  = e >> 5;
                int c4 = e & 31;
                *(float4*)(dst + r * NTILE + c4 * 4) = pf[q];
            }
        }
        __syncthreads();

        if (kt == 7) {
            // Fold tile tt: t1 = fl(nf + c_k); t2 = fl(t1 - fl(2*s)).
            // Ascending code order + strict '<' keeps FIRST minimal index.
            const int cbase = tt * NTILE + j * 8;
            #pragma unroll
            for (int p = 0; p < 4; ++p) {
                float ck0 = g_c[cbase + 2 * p];
                float ck1 = g_c[cbase + 2 * p + 1];
                #pragma unroll
                for (int m = 0; m < 8; ++m) {
                    float2 s2 = unpack2(acc2[m][p]);
                    float t1a = __fadd_rn(nf_m[m], ck0);
                    float va  = __fsub_rn(t1a, __fmul_rn(2.f, s2.x));
                    if (va < bv[m]) { bv[m] = va; bi[m] = cbase + 2 * p; }
                    float t1b = __fadd_rn(nf_m[m], ck1);
                    float vb  = __fsub_rn(t1b, __fmul_rn(2.f, s2.y));
                    if (vb < bv[m]) { bv[m] = vb; bi[m] = cbase + 2 * p + 1; }
                }
            }
            #pragma unroll
            for (int m = 0; m < 8; ++m)
                #pragma unroll
                for (int p = 0; p < 4; ++p) acc2[m][p] = 0ull;
        }
    }

    __syncthreads();
    #pragma unroll
    for (int m = 0; m < 8; ++m) {
        int r = i + 16 * m;
        sBv[r * 16 + j] = bv[m];
        sBi[r * 16 + j] = bi[m];
    }
    __syncthreads();

    if (t < MTILE) {
        float best = sBv[t * 16];
        int   bidx = sBi[t * 16];
        #pragma unroll
        for (int jj = 1; jj < 16; ++jj) {
            float v = sBv[t * 16 + jj];
            int  idx = sBi[t * 16 + jj];
            if (v < best || (v == best && idx < bidx)) { best = v; bidx = idx; }
        }
        sIdx[t] = bidx;
    }
    __syncthreads();

    // Epilogue: gather q = 0.5*dictT[idx][d] (exact halving; coalesced reads),
    // write output, accumulate loss partial.
    float lsum = 0.f;
    for (int e = t; e < MTILE * D_DIM; e += THREADS) {
        int r = e >> 8;           // D_DIM == 256
        int d = e & 255;
        int idx = sIdx[r];
        float q  = 0.5f * g_dictT[idx * D_DIM + d];
        float xv = sA[r * ASTRIDE + d];
        float df = xv - q;
        lsum = fmaf(df, df, lsum);
        out[(row0 + r) * D_DIM + d] = q;
    }

    // Block reduce lsum -> double atomic
    #pragma unroll
    for (int o = 16; o > 0; o >>= 1)
        lsum += __shfl_xor_sync(0xffffffffu, lsum, o);
    __syncthreads();                       // done reading sBv; safe to reuse
    if ((t & 31) == 0) sBv[t >> 5] = lsum;
    __syncthreads();
    if (t == 0) {
        float s = 0.f;
        #pragma unroll
        for (int w = 0; w < THREADS / 32; ++w) s += sBv[w];
        atomicAdd(&g_loss, (double)s);
    }
}

// ---------------------------------------------------------------------------
// Kernel 3: loss = 1.25 * mean((x - q)^2)   (dict_loss + 0.25*commitment,
// both numerically identical since stop_gradient is identity in value)
// ---------------------------------------------------------------------------
__global__ void vq_finalize(float* __restrict__ out, int loss_idx) {
    out[loss_idx] = (float)(1.25 * g_loss * (1.0 / (double)(N_ROWS * D_DIM)));
}

static const int SMEM_BYTES =
    (MTILE * ASTRIDE + 2 * KCHUNK * NTILE + MTILE * 16) * (int)sizeof(float)
    + MTILE * 16 * (int)sizeof(int) + MTILE * (int)sizeof(int)
    + MTILE * (int)sizeof(float);

extern "C" void kernel_launch(void* const* d_in, const int* in_sizes, int n_in,
                              void* d_out, int out_size) {
    const float* x    = (const float*)d_in[0];
    const float* dict = (const float*)d_in[1];
    float* out = (float*)d_out;

    cudaFuncSetAttribute(vq_main, cudaFuncAttributeMaxDynamicSharedMemorySize,
                         SMEM_BYTES);

    vq_transpose<<<dim3(K_CODES / 32, D_DIM / 32), 256>>>(dict);
    vq_norms<<<(K_CODES + 255) / 256, 256>>>(dict);
    vq_main<<<N_ROWS / MTILE, THREADS, SMEM_BYTES>>>(x, dict, out);
    vq_finalize<<<1, 1>>>(out, out_size - 1);
}